// round 17
// baseline (speedup 1.0000x reference)
#include <cuda_runtime.h>
#include <cuda_bf16.h>
#include <math.h>
#include <float.h>
#include <stdint.h>

#define BATCH  8
#define LSEQ   4096
#define DMODEL 512
#define TOPK   8
#define NGRP   64
#define WSZ    (DMODEL * DMODEL)

// ---------------- scratch (static device globals; no allocations) ----------------
__device__ float  g_u  [BATCH * DMODEL * LSEQ];   // u = H x, channel-major [B,D,L]
__device__ float  g_y  [BATCH * LSEQ * DMODEL];   // y = Wov x, [B,L,D]
__device__ float  g_xt [BATCH * DMODEL * LSEQ];   // x transposed, channel-major
__device__ float2 g_spart[BATCH * NGRP * LSEQ];
__device__ float2 g_sred [BATCH * LSEQ];
__device__ float  g_weights[BATCH * TOPK];
__device__ int    g_delays [BATCH * TOPK];
__device__ float  g_bov[DMODEL];
// bf16 hi/lo operands: slot 0 = H (=Wk^T Wq), slot 2 = Wov (=Wo Wv)
__device__ __nv_bfloat16 g_xhi [BATCH * LSEQ * DMODEL];
__device__ __nv_bfloat16 g_xlo [BATCH * LSEQ * DMODEL];
__device__ __nv_bfloat16 g_whi [3 * WSZ];
__device__ __nv_bfloat16 g_wlo [3 * WSZ];

// ====================== helpers ======================
__device__ __forceinline__ uint32_t smem_u32(const void* p) {
    uint32_t a;
    asm("{ .reg .u64 t; cvta.to.shared.u64 t, %1; cvt.u32.u64 %0, t; }" : "=r"(a) : "l"(p));
    return a;
}
#define SWZ(off) ((off) ^ (((off) >> 3) & 0x70))

__device__ __forceinline__ void cpa16(uint32_t dst, const void* src) {
    asm volatile("cp.async.ca.shared.global [%0], [%1], 16;" :: "r"(dst), "l"(src));
}
#define CPA_COMMIT() asm volatile("cp.async.commit_group;" ::: "memory")
#define CPA_WAIT(N)  asm volatile("cp.async.wait_group %0;" :: "n"(N) : "memory")

__device__ __forceinline__ void ldmA(uint32_t* a, uint32_t addr) {
    asm volatile("ldmatrix.sync.aligned.m8n8.x4.shared.b16 {%0,%1,%2,%3}, [%4];"
        : "=r"(a[0]), "=r"(a[1]), "=r"(a[2]), "=r"(a[3]) : "r"(addr));
}
__device__ __forceinline__ void ldmB(uint32_t* b, uint32_t addr) {
    asm volatile("ldmatrix.sync.aligned.m8n8.x2.shared.b16 {%0,%1}, [%2];"
        : "=r"(b[0]), "=r"(b[1]) : "r"(addr));
}
__device__ __forceinline__ void mma16816(float* c, const uint32_t* a, const uint32_t* b) {
    asm volatile("mma.sync.aligned.m16n8k16.row.col.f32.bf16.bf16.f32 "
        "{%0,%1,%2,%3}, {%4,%5,%6,%7}, {%8,%9}, {%0,%1,%2,%3};"
        : "+f"(c[0]), "+f"(c[1]), "+f"(c[2]), "+f"(c[3])
        : "r"(a[0]), "r"(a[1]), "r"(a[2]), "r"(a[3]), "r"(b[0]), "r"(b[1]));
}

// ====================== bf16x3 mma.sync fused GEMM (512 threads / 16 warps) ======================
// Computes BOTH u = H x  (mb 0..3, out [B,D,L])  AND  y = Wov x (mb 4..7, out [B,L,D]).
#define BM 128
#define BN 128
#define BK 64
#define NCHUNK (DMODEL / BK)       // 8
#define TSZ     16384
#define OFF_AHI 0
#define OFF_ALO (TSZ)
#define OFF_BHI (2 * TSZ)
#define OFF_BLO (3 * TSZ)
#define STAGE_BYTES (4 * TSZ)              // 65536
#define NSTAGE 3
#define GEMM_DSMEM  (NSTAGE * STAGE_BYTES + 1024)
#define GTH 512

__global__ __launch_bounds__(GTH, 1)
void gemm_uy_kernel(const __nv_bfloat16* __restrict__ Whi,
                    const __nv_bfloat16* __restrict__ Wlo,
                    const __nv_bfloat16* __restrict__ Bhi,
                    const __nv_bfloat16* __restrict__ Blo,
                    float* __restrict__ uout, float* __restrict__ yout)
{
    extern __shared__ char dsm[];
    const int tid  = threadIdx.x;
    const int wid  = tid >> 5;                 // 0..15
    const int lane = tid & 31;
    const int wm   = wid >> 2;                 // 0..3  (32 m rows)
    const int wn   = wid & 3;                  // 0..3  (32 n cols)
    const int b  = blockIdx.z;
    const int mb = blockIdx.y;                 // 0..7
    const bool isY = (mb >= 4);
    const int m0 = (isY ? (mb - 4) : mb) * BM;
    const int n0 = blockIdx.x * BN;

    uint32_t sbase = (smem_u32(dsm) + 1023u) & ~1023u;

    const __nv_bfloat16* aHi = Whi + (isY ? 2 * (size_t)WSZ : 0) + (size_t)m0 * DMODEL;
    const __nv_bfloat16* aLo = Wlo + (isY ? 2 * (size_t)WSZ : 0) + (size_t)m0 * DMODEL;
    const __nv_bfloat16* bHi = Bhi + ((size_t)b * LSEQ + n0) * DMODEL;
    const __nv_bfloat16* bLo = Blo + ((size_t)b * LSEQ + n0) * DMODEL;

    auto load_chunk = [&](int st, int k0) {
        uint32_t sb = sbase + st * STAGE_BYTES;
#pragma unroll
        for (int it = 0; it < 2; ++it) {
            int idx = tid + it * GTH;              // 0..1023
            int row = idx >> 3, q = idx & 7;
            uint32_t sw = SWZ((uint32_t)(row * 128 + q * 16));
            size_t go = (size_t)row * DMODEL + k0 + q * 8;
            cpa16(sb + OFF_AHI + sw, aHi + go);
            cpa16(sb + OFF_ALO + sw, aLo + go);
            cpa16(sb + OFF_BHI + sw, bHi + go);
            cpa16(sb + OFF_BLO + sw, bLo + go);
        }
        CPA_COMMIT();
    };

    float c[2][4][4];
#pragma unroll
    for (int i = 0; i < 2; ++i)
#pragma unroll
        for (int j = 0; j < 4; ++j)
#pragma unroll
            for (int r = 0; r < 4; ++r) c[i][j][r] = 0.f;

    load_chunk(0, 0);
    load_chunk(1, BK);

    // single-barrier pipeline (stage ch+2 written only after top sync of ch)
    for (int ch = 0; ch < NCHUNK; ++ch) {
        int st = ch % NSTAGE;
        if (ch < NCHUNK - 1) { CPA_WAIT(1); }
        else                 { CPA_WAIT(0); }
        __syncthreads();
        if (ch + 2 < NCHUNK) load_chunk((ch + 2) % NSTAGE, (ch + 2) * BK);

        uint32_t sb = sbase + st * STAGE_BYTES;
        uint32_t aHiB = sb + OFF_AHI, aLoB = sb + OFF_ALO;
        uint32_t bHiB = sb + OFF_BHI, bLoB = sb + OFF_BLO;

#pragma unroll
        for (int ks = 0; ks < 4; ++ks) {
            uint32_t bh[4][2], bl[4][2];
#pragma unroll
            for (int ni = 0; ni < 4; ++ni) {
                uint32_t rowb = wn * 32 + ni * 8 + (lane & 7);
                uint32_t cb   = ks * 32 + (((lane >> 3) & 1) << 4);
                uint32_t off  = SWZ(rowb * 128 + cb);
                ldmB(bh[ni], bHiB + off);
                ldmB(bl[ni], bLoB + off);
            }
#pragma unroll
            for (int mi = 0; mi < 2; ++mi) {
                uint32_t rowa = wm * 32 + mi * 16 + (lane & 15);
                uint32_t ca   = ks * 32 + ((lane >> 4) << 4);
                uint32_t off  = SWZ(rowa * 128 + ca);
                uint32_t ah[4], al[4];
                ldmA(ah, aHiB + off);
                ldmA(al, aLoB + off);
#pragma unroll
                for (int ni = 0; ni < 4; ++ni) {
                    mma16816(c[mi][ni], ah, bh[ni]);
                    mma16816(c[mi][ni], ah, bl[ni]);
                    mma16816(c[mi][ni], al, bh[ni]);
                }
            }
        }
    }

    const int r  = lane >> 2;
    const int q2 = (lane & 3) << 1;
    if (!isY) {
        // u: [B, D, L]
#pragma unroll
        for (int mi = 0; mi < 2; ++mi) {
            int m = m0 + wm * 32 + mi * 16 + r;
#pragma unroll
            for (int ni = 0; ni < 4; ++ni) {
                int n = n0 + wn * 32 + ni * 8 + q2;
                float* p = uout + ((size_t)(b * DMODEL + m) << 12) + n;
                *(float2*)p = make_float2(c[mi][ni][0], c[mi][ni][1]);
                float* p2 = p + (8 << 12);
                *(float2*)p2 = make_float2(c[mi][ni][2], c[mi][ni][3]);
            }
        }
    } else {
        // y: [B, L, D] via smem transpose (bov added later in gather)
        float* tileT = (float*)dsm;   // 128 n-rows x 132 floats
        __syncthreads();              // mainloop has no trailing barrier
#pragma unroll
        for (int mi = 0; mi < 2; ++mi) {
            int ml = wm * 32 + mi * 16 + r;
#pragma unroll
            for (int ni = 0; ni < 4; ++ni) {
                int nl = wn * 32 + ni * 8 + q2;
                tileT[nl * 132 + ml]           = c[mi][ni][0];
                tileT[(nl + 1) * 132 + ml]     = c[mi][ni][1];
                tileT[nl * 132 + ml + 8]       = c[mi][ni][2];
                tileT[(nl + 1) * 132 + ml + 8] = c[mi][ni][3];
            }
        }
        __syncthreads();
#pragma unroll
        for (int it = 0; it < 8; ++it) {
            int idx = tid + it * GTH;
            int nl = idx >> 5;
            int c4 = (idx & 31) << 2;
            float4 v = *(float4*)&tileT[nl * 132 + c4];
            *(float4*)(yout + (((size_t)b * LSEQ + n0 + nl) << 9) + m0 + c4) = v;
        }
    }
}

// ====================== convert x: bf16 hi/lo + fp32 transpose ======================
__global__ __launch_bounds__(256)
void convert_x_kernel(const float* __restrict__ hs)
{
    __shared__ float tile[32][33];
    const int tx = threadIdx.x;
    const int ty = threadIdx.y;
    const int b  = blockIdx.z;
    const int d0 = blockIdx.y * 32;
    const int l0 = blockIdx.x * 32;

#pragma unroll
    for (int i = 0; i < 4; ++i) {
        int l = l0 + ty + i * 8;
        size_t gi = (((size_t)b * LSEQ + l) << 9) + d0 + tx;
        float v = hs[gi];
        tile[ty + i * 8][tx] = v;
        __nv_bfloat16 h  = __float2bfloat16(v);
        __nv_bfloat16 lo = __float2bfloat16(v - __bfloat162float(h));
        g_xhi[gi] = h;
        g_xlo[gi] = lo;
    }
    __syncthreads();

#pragma unroll
    for (int i = 0; i < 4; ++i) {
        int d = d0 + ty + i * 8;
        g_xt[(((size_t)b * DMODEL + d) << 12) + l0 + tx] = tile[tx][ty + i * 8];
    }
}

// ====================== weight prep: H = Wk^T Wq (z=0) / Wov = Wo Wv + bov (z=1) ======================
__global__ __launch_bounds__(256)
void wprep_kernel(const float* __restrict__ Wk, const float* __restrict__ Wq,
                  const float* __restrict__ Wo, const float* __restrict__ Wv,
                  const float* __restrict__ bv, const float* __restrict__ bo)
{
    const int z = blockIdx.z;
    if (blockIdx.x == 8) {
        if (z == 1) {
            int w = threadIdx.x >> 5, lane = threadIdx.x & 31;
#pragma unroll
            for (int rr = 0; rr < 8; ++rr) {
                int m = blockIdx.y * 64 + w * 8 + rr;
                const float* row = Wo + (size_t)m * DMODEL;
                float s = 0.f;
                for (int c = lane; c < DMODEL; c += 32) s += row[c] * bv[c];
#pragma unroll
                for (int o = 16; o; o >>= 1) s += __shfl_xor_sync(0xffffffffu, s, o);
                if (lane == 0) g_bov[m] = s + bo[m];
            }
        }
        return;
    }

    __shared__ float As[32][68];
    __shared__ float Bs[32][68];
    const int tid = threadIdx.x;
    const int tx = tid & 15, ty = tid >> 4;
    const int m0 = blockIdx.y * 64, n0 = blockIdx.x * 64;

    float c[4][4];
#pragma unroll
    for (int i = 0; i < 4; ++i)
#pragma unroll
        for (int j = 0; j < 4; ++j) c[i][j] = 0.f;

    for (int cc = 0; cc < DMODEL; cc += 32) {
        if (z == 0) {
#pragma unroll
            for (int it = 0; it < 2; ++it) {
                int idx = tid + it * 256;
                int d2 = idx >> 4; int q4 = (idx & 15) << 2;
                *(float4*)&As[d2][q4] = *(const float4*)&Wk[(size_t)(cc + d2) * DMODEL + m0 + q4];
                *(float4*)&Bs[d2][q4] = *(const float4*)&Wq[(size_t)(cc + d2) * DMODEL + n0 + q4];
            }
        } else {
#pragma unroll
            for (int it = 0; it < 2; ++it) {
                int idx = tid + it * 256;
                int m = idx >> 3; int cq = (idx & 7) << 2;
                float4 v = *(const float4*)&Wo[(size_t)(m0 + m) * DMODEL + cc + cq];
                As[cq + 0][m] = v.x; As[cq + 1][m] = v.y;
                As[cq + 2][m] = v.z; As[cq + 3][m] = v.w;
            }
#pragma unroll
            for (int it = 0; it < 2; ++it) {
                int idx = tid + it * 256;
                int c2 = idx >> 4; int nq = (idx & 15) << 2;
                *(float4*)&Bs[c2][nq] = *(const float4*)&Wv[(size_t)(cc + c2) * DMODEL + n0 + nq];
            }
        }
        __syncthreads();
#pragma unroll
        for (int k = 0; k < 32; ++k) {
            float a[4], bb[4];
#pragma unroll
            for (int i = 0; i < 4; ++i) a[i] = As[k][ty * 4 + i];
#pragma unroll
            for (int j = 0; j < 4; ++j) bb[j] = Bs[k][tx * 4 + j];
#pragma unroll
            for (int i = 0; i < 4; ++i)
#pragma unroll
                for (int j = 0; j < 4; ++j) c[i][j] += a[i] * bb[j];
        }
        __syncthreads();
    }

    size_t slot = (z == 0) ? 0 : 2 * (size_t)WSZ;
#pragma unroll
    for (int i = 0; i < 4; ++i) {
        int m = m0 + ty * 4 + i;
#pragma unroll
        for (int j = 0; j < 4; ++j) {
            int n = n0 + tx * 4 + j;
            float v = c[i][j];
            __nv_bfloat16 h  = __float2bfloat16(v);
            __nv_bfloat16 lo = __float2bfloat16(v - __bfloat162float(h));
            g_whi[slot + (size_t)m * DMODEL + n] = h;
            g_wlo[slot + (size_t)m * DMODEL + n] = lo;
        }
    }
}

// ====================== radix-16 FFT machinery ======================
#define FPAD(i) ((i) + ((i) >> 4) + ((i) >> 8))
#define FFT_BUF 4368

__device__ __forceinline__ float2 cmul(float2 a, float2 b) {
    return make_float2(a.x * b.x - a.y * b.y, a.x * b.y + a.y * b.x);
}
__device__ __forceinline__ int rev16_12(int i) {
    return ((i & 15) << 8) | (i & 0xF0) | ((i >> 8) & 15);
}

template<bool INV>
__device__ __forceinline__ void dft4(float2 a, float2 b, float2 c, float2 d,
                                     float2& o0, float2& o1, float2& o2, float2& o3)
{
    float2 e0 = make_float2(a.x + c.x, a.y + c.y);
    float2 e1 = make_float2(a.x - c.x, a.y - c.y);
    float2 e2 = make_float2(b.x + d.x, b.y + d.y);
    float2 e3 = make_float2(b.x - d.x, b.y - d.y);
    o0 = make_float2(e0.x + e2.x, e0.y + e2.y);
    o2 = make_float2(e0.x - e2.x, e0.y - e2.y);
    if (!INV) {
        o1 = make_float2(e1.x + e3.y, e1.y - e3.x);
        o3 = make_float2(e1.x - e3.y, e1.y + e3.x);
    } else {
        o1 = make_float2(e1.x - e3.y, e1.y + e3.x);
        o3 = make_float2(e1.x + e3.y, e1.y - e3.x);
    }
}

template<bool INV>
__device__ __forceinline__ void dft16(float2* x)
{
    const float c1 = 0.92387953251128674f;
    const float s1 = 0.38268343236508978f;
    const float r2 = 0.70710678118654752f;
    const float si = INV ? 1.f : -1.f;
    auto tm = [](float2 v, float wr, float wi) {
        return make_float2(v.x * wr - v.y * wi, v.x * wi + v.y * wr);
    };
    float2 A[16];
#pragma unroll
    for (int t0 = 0; t0 < 4; ++t0)
        dft4<INV>(x[t0], x[t0 + 4], x[t0 + 8], x[t0 + 12],
                  A[0 + t0], A[4 + t0], A[8 + t0], A[12 + t0]);
    A[4 + 1]  = tm(A[4 + 1],  c1,  si * s1);
    A[4 + 2]  = tm(A[4 + 2],  r2,  si * r2);
    A[4 + 3]  = tm(A[4 + 3],  s1,  si * c1);
    A[8 + 1]  = tm(A[8 + 1],  r2,  si * r2);
    A[8 + 2]  = tm(A[8 + 2],  0.f, si);
    A[8 + 3]  = tm(A[8 + 3], -r2,  si * r2);
    A[12 + 1] = tm(A[12 + 1], s1,  si * c1);
    A[12 + 2] = tm(A[12 + 2], -r2, si * r2);
    A[12 + 3] = tm(A[12 + 3], -c1, -si * s1);
#pragma unroll
    for (int u0 = 0; u0 < 4; ++u0)
        dft4<INV>(A[u0 * 4], A[u0 * 4 + 1], A[u0 * 4 + 2], A[u0 * 4 + 3],
                  x[u0], x[u0 + 4], x[u0 + 8], x[u0 + 12]);
}

template<bool INV>
__device__ __forceinline__ void fft4096_r16(float2* buf, const float2* tw, int tid)
{
#pragma unroll
    for (int s = 0; s < 3; ++s) {
        const int Q = 1 << (4 * s);
        int q  = tid & (Q - 1);
        int i0 = ((tid >> (4 * s)) << (4 * s + 4)) + q;
        float2 w1 = tw[q << (8 - 4 * s)];
        float2 x[16];
        x[0] = buf[FPAD(i0)];
        float2 wt = w1;
#pragma unroll
        for (int t = 1; t < 16; ++t) {
            x[t] = cmul(buf[FPAD(i0 + t * Q)], wt);
            wt = cmul(wt, w1);
        }
        dft16<INV>(x);
#pragma unroll
        for (int u = 0; u < 16; ++u) buf[FPAD(i0 + u * Q)] = x[u];
        __syncthreads();
    }
}

// Forward FFT of z = u + i*x per channel, accumulate Uf*conj(Xf) over 8 channels.
__global__ void fftcorr_kernel()
{
    __shared__ float2 buf[FFT_BUF];
    __shared__ float2 tw[256];

    const int tid = threadIdx.x;
    const int g = blockIdx.x, b = blockIdx.y;

    {
        float s, c;
        sincosf(6.283185307179586f * (float)tid / 4096.0f, &s, &c);
        tw[tid] = make_float2(c, -s);
    }

    float2 acc[16];
#pragma unroll
    for (int j = 0; j < 16; ++j) acc[j] = make_float2(0.f, 0.f);

    for (int cc = 0; cc < 8; ++cc) {
        int ch = g * 8 + cc;
        const float* up = g_u  + (((size_t)b * DMODEL + ch) << 12);
        const float* xp = g_xt + (((size_t)b * DMODEL + ch) << 12);

        __syncthreads();
#pragma unroll
        for (int j = 0; j < 16; ++j) {
            int n = tid + 256 * j;
            buf[FPAD(rev16_12(n))] = make_float2(up[n], xp[n]);
        }
        __syncthreads();

        fft4096_r16<false>(buf, tw, tid);

#pragma unroll
        for (int j = 0; j < 16; ++j) {
            int f = tid + 256 * j;
            float2 Zf = buf[FPAD(f)];
            float2 Zm = buf[FPAD((4096 - f) & 4095)];
            float2 U  = make_float2(0.5f * (Zf.x + Zm.x), 0.5f * (Zf.y - Zm.y));
            float dx = Zf.x - Zm.x, dy = Zf.y + Zm.y;
            float2 Xc = make_float2(0.5f * dy, -0.5f * dx);
            acc[j].x += U.x * Xc.x + U.y * Xc.y;
            acc[j].y += U.y * Xc.x - U.x * Xc.y;
        }
    }
#pragma unroll
    for (int j = 0; j < 16; ++j)
        g_spart[(((size_t)b * NGRP + g) << 12) + tid + 256 * j] = acc[j];
}

__global__ void reduce_kernel()
{
    const int f = blockIdx.x * 256 + threadIdx.x;
    const int b = blockIdx.y;
    const float2* sp = g_spart + (((size_t)b * NGRP) << 12) + f;
    float2 s = make_float2(0.f, 0.f);
#pragma unroll 8
    for (int gp = 0; gp < NGRP; ++gp) {
        float2 v = sp[(size_t)gp << 12];
        s.x += v.x; s.y += v.y;
    }
    g_sred[((size_t)b << 12) + f] = s;
}

// Inverse FFT of reduced spectrum + fused top-k + softmax.
__global__ void ifft_topk_kernel()
{
    __shared__ float2 buf[FFT_BUF];
    __shared__ float2 tw[256];
    __shared__ float rv[256];
    __shared__ int   ri[256];
    __shared__ float wv[TOPK];
    __shared__ int   wi[TOPK];

    const int tid = threadIdx.x;
    const int b = blockIdx.x;

    {
        float s, c;
        sincosf(6.283185307179586f * (float)tid / 4096.0f, &s, &c);
        tw[tid] = make_float2(c, s);
    }
    __syncthreads();

#pragma unroll
    for (int j = 0; j < 16; ++j) {
        int f = tid + 256 * j;
        buf[FPAD(rev16_12(f))] = g_sred[((size_t)b << 12) + f];
    }
    __syncthreads();

    fft4096_r16<true>(buf, tw, tid);

    for (int r = 0; r < TOPK; ++r) {
        float best = -FLT_MAX;
        int bi = 0x7fffffff;
#pragma unroll
        for (int j = 0; j < 16; ++j) {
            int i = tid + 256 * j;
            float v = buf[FPAD(i)].x;
            if (v > best) { best = v; bi = i; }
        }
        rv[tid] = best; ri[tid] = bi;
        __syncthreads();
        for (int s = 128; s > 0; s >>= 1) {
            if (tid < s) {
                if (rv[tid + s] > rv[tid] ||
                    (rv[tid + s] == rv[tid] && ri[tid + s] < ri[tid])) {
                    rv[tid] = rv[tid + s]; ri[tid] = ri[tid + s];
                }
            }
            __syncthreads();
        }
        if (tid == 0) { wv[r] = rv[0]; wi[r] = ri[0]; buf[FPAD(ri[0])].x = -FLT_MAX; }
        __syncthreads();
    }

    if (tid == 0) {
        const float scale = 1.0f / (4096.0f * 512.0f);
        float mx = wv[0] * scale;
        float e[TOPK], sum = 0.f;
#pragma unroll
        for (int i = 0; i < TOPK; ++i) { e[i] = expf(wv[i] * scale - mx); sum += e[i]; }
        float inv = 1.0f / sum;
#pragma unroll
        for (int i = 0; i < TOPK; ++i) {
            g_weights[b * TOPK + i] = e[i] * inv;
            g_delays [b * TOPK + i] = wi[i];
        }
    }
}

// ====================== final gather on y: out = sum_i w_i y(l+d_i) + bov ======================
__global__ __launch_bounds__(128)
void gathery_kernel(float* __restrict__ out)
{
    __shared__ float ws[TOPK];
    __shared__ int   ds[TOPK];
    const int tid = threadIdx.x;
    const int l = blockIdx.x, b = blockIdx.y;

    if (tid < TOPK) {
        ws[tid] = g_weights[b * TOPK + tid];
        ds[tid] = g_delays [b * TOPK + tid];
    }
    __syncthreads();

    const float4* yb = (const float4*)(g_y + (((size_t)b * LSEQ) << 9));
    float4 acc = ((const float4*)g_bov)[tid];
#pragma unroll
    for (int i = 0; i < TOPK; ++i) {
        int t = (l + ds[i]) & (LSEQ - 1);
        float4 v = yb[t * 128 + tid];
        float w = ws[i];
        acc.x += w * v.x; acc.y += w * v.y; acc.z += w * v.z; acc.w += w * v.w;
    }
    ((float4*)(out + (((size_t)b * LSEQ + l) << 9)))[tid] = acc;
}

// =====================================================================
extern "C" void kernel_launch(void* const* d_in, const int* in_sizes, int n_in,
                              void* d_out, int out_size)
{
    const float* hs = (const float*)d_in[0];
    const float* Wq = (const float*)d_in[1];
    const float* Wk = (const float*)d_in[3];
    const float* Wv = (const float*)d_in[5];
    const float* bv = (const float*)d_in[6];
    const float* Wo = (const float*)d_in[7];
    const float* bo = (const float*)d_in[8];
    float* out = (float*)d_out;

    void *pu, *py, *pxhi, *pxlo, *pwhi, *pwlo;
    cudaGetSymbolAddress(&pu,   g_u);
    cudaGetSymbolAddress(&py,   g_y);
    cudaGetSymbolAddress(&pxhi, g_xhi);
    cudaGetSymbolAddress(&pxlo, g_xlo);
    cudaGetSymbolAddress(&pwhi, g_whi);
    cudaGetSymbolAddress(&pwlo, g_wlo);

    cudaFuncSetAttribute(gemm_uy_kernel,
                         cudaFuncAttributeMaxDynamicSharedMemorySize, GEMM_DSMEM);

    // 1. x prep + weight folding (H, Wov, bov)
    convert_x_kernel<<<dim3(LSEQ / 32, DMODEL / 32, BATCH), dim3(32, 8)>>>(hs);
    wprep_kernel<<<dim3(9, 8, 2), 256>>>(Wk, Wq, Wo, Wv, bv, bo);

    // 2. fused GEMM: u = H x (-> [B,D,L])  and  y = Wov x (-> [B,L,D])
    dim3 gg(LSEQ / BN, 8, BATCH);
    gemm_uy_kernel<<<gg, GTH, GEMM_DSMEM>>>(
        (const __nv_bfloat16*)pwhi, (const __nv_bfloat16*)pwlo,
        (const __nv_bfloat16*)pxhi, (const __nv_bfloat16*)pxlo,
        (float*)pu, (float*)py);

    // 3. cross-correlation spectrum of (u, x) + reduce + fused iFFT/top-k
    fftcorr_kernel<<<dim3(NGRP, BATCH), 256>>>();
    reduce_kernel<<<dim3(LSEQ / 256, BATCH), 256>>>();
    ifft_topk_kernel<<<BATCH, 256>>>();

    // 4. final gather on y -> out (+bov)
    gathery_kernel<<<dim3(LSEQ, BATCH), 128>>>(out);
}